// round 15
// baseline (speedup 1.0000x reference)
#include <cuda_runtime.h>
#include <math.h>

// ---------------- problem constants ----------------
#define BB 64
#define TT 32
#define HH 512
#define MM 256
#define WWD 64
#define RR 4
#define IFACE 471
#define G4H 2048
#define NNOUT 768
#define CLIPV 20.0f
#define DELTA 1e-6f
#define NBLK 128            // persistent grid size (<= 148 SMs, 1 block/SM guaranteed)

// ---------------- device state ----------------
__device__ float g_xprojp[BB*TT*G4H];   // permuted x-projection incl. biases (immutable in loop)
__device__ float g_p1h[BB*G4H];         // lstm1 partial: W1p[:,512:] @ h1_old
__device__ float g_h0buf[2*BB*HH];      // parity buffers for h0
__device__ float g_in1[2*BB*1024];      // parity buffers for [h0 | h1]
__device__ float g_c0[BB*HH];           // init handoff only (state lives in registers)
__device__ float g_c1[BB*HH];
__device__ float g_outb[BB*HH];
__device__ float g_mem[BB*MM*WWD];
__device__ float g_link[BB*MM*MM];
__device__ float g_prec[BB*MM];
__device__ float g_rw[BB*RR*MM];
__device__ float g_ww[BB*MM];
__device__ float g_usage[BB*MM];
__device__ float g_ys[BB*TT*NNOUT];
__device__ float g_W0p[G4H*512];        // permuted Whh0  (row n'=4h+g)
__device__ float g_Wih0p[G4H*256];      // permuted Wih0[:, :256]
__device__ float g_W1p[G4H*1024];       // permuted [Wih1 | Whh1]
__device__ float g_WifT[512*480];       // transposed Wif: [k][i], i padded to 480
__device__ float g_bp0[G4H];
__device__ float g_bp1[G4H];
__device__ unsigned int g_bars[128];    // grid-barrier counters (zeroed each replay)

// ---------------- fast-math helpers ----------------
__device__ __forceinline__ float sigf(float x) {
    return __fdividef(1.f, 1.f + __expf(-x));
}
__device__ __forceinline__ float tanhfast(float x) {
    float e = __expf(-2.f * fabsf(x));
    float r = __fdividef(1.f - e, 1.f + e);
    return copysignf(r, x);
}
__device__ __forceinline__ float splusf(float x) {
    return fmaxf(x, 0.f) + log1pf(__expf(-fabsf(x)));
}

// ---------------- software grid barrier (all NBLK blocks resident) --------
__device__ __forceinline__ void grid_bar(int idx) {
    __syncthreads();
    if (threadIdx.x == 0) {
        __threadfence();
        atomicAdd(&g_bars[idx], 1u);
        while (atomicAdd(&g_bars[idx], 0u) < (unsigned)NBLK) __nanosleep(64);
    }
    __syncthreads();
}

// ---------------- generic C = A * B^T (B row-major [N][K]) ----------------
#define TKC 16
__global__ void __launch_bounds__(256) gemm_bt(
                        const float* __restrict__ A, int lda,
                        const float* __restrict__ Bw, int ldb,
                        float* __restrict__ C, int ldc,
                        int N, int Klen,
                        const float* __restrict__ bias0,
                        int tanhA)
{
    __shared__ float As[TKC][68];
    __shared__ __align__(16) float Bs[TKC][34];

    const int tid = threadIdx.x;
    const int tx = tid & 15;
    const int ty = tid >> 4;
    const int row0 = blockIdx.y * 64;
    const int n0 = blockIdx.x * 32;

    float acc[4][2] = {};

    const int la_m = tid >> 2;
    const int la_k = (tid & 3) * 4;
    const int lb_n = tid >> 3;
    const int lb_k = (tid & 7) * 2;

    const float* Ab = A + (long)(row0 + la_m) * lda + la_k;
    const bool bvalid = (n0 + lb_n) < N;
    const float* Bb = Bw + (long)(n0 + lb_n) * ldb + lb_k;

    float a0 = Ab[0], a1 = Ab[1], a2 = Ab[2], a3 = Ab[3];
    float b0 = 0.f, b1 = 0.f;
    if (bvalid) { b0 = Bb[0]; b1 = Bb[1]; }

    for (int k0 = 0; k0 < Klen; k0 += TKC) {
        float sa0 = a0, sa1 = a1, sa2 = a2, sa3 = a3;
        if (tanhA) { sa0 = tanhfast(sa0); sa1 = tanhfast(sa1);
                     sa2 = tanhfast(sa2); sa3 = tanhfast(sa3); }
        __syncthreads();
        As[la_k + 0][la_m] = sa0; As[la_k + 1][la_m] = sa1;
        As[la_k + 2][la_m] = sa2; As[la_k + 3][la_m] = sa3;
        Bs[lb_k][lb_n] = b0; Bs[lb_k + 1][lb_n] = b1;
        __syncthreads();
        if (k0 + TKC < Klen) {
            a0 = Ab[k0 + TKC + 0]; a1 = Ab[k0 + TKC + 1];
            a2 = Ab[k0 + TKC + 2]; a3 = Ab[k0 + TKC + 3];
            if (bvalid) { b0 = Bb[k0 + TKC]; b1 = Bb[k0 + TKC + 1]; }
        }
        #pragma unroll
        for (int kk = 0; kk < TKC; kk++) {
            float4 av = *(const float4*)&As[kk][ty * 4];
            float2 bv = *(const float2*)&Bs[kk][tx * 2];
            acc[0][0] += av.x * bv.x; acc[0][1] += av.x * bv.y;
            acc[1][0] += av.y * bv.x; acc[1][1] += av.y * bv.y;
            acc[2][0] += av.z * bv.x; acc[2][1] += av.z * bv.y;
            acc[3][0] += av.w * bv.x; acc[3][1] += av.w * bv.y;
        }
    }
    #pragma unroll
    for (int i = 0; i < 4; i++) {
        int m = row0 + ty * 4 + i;
        #pragma unroll
        for (int j = 0; j < 2; j++) {
            int n = n0 + tx * 2 + j;
            if (n < N) {
                float v = acc[i][j];
                if (bias0) v += bias0[n];
                C[(long)m * ldc + n] = v;
            }
        }
    }
}

// ---------------- init: permute weights + init state + zero barriers -------
__global__ void __launch_bounds__(256) init_kernel(
                            const float* __restrict__ h0in,
                            const float* __restrict__ Wih0,
                            const float* __restrict__ Whh0,
                            const float* __restrict__ bih0,
                            const float* __restrict__ bhh0,
                            const float* __restrict__ Wih1,
                            const float* __restrict__ Whh1,
                            const float* __restrict__ bih1,
                            const float* __restrict__ bhh1,
                            const float* __restrict__ Wif)
{
    int i = blockIdx.x * 256 + threadIdx.x;
    if (i < 128) g_bars[i] = 0u;
    if (i < BB * MM * MM) g_link[i] = 0.f;
    if (i < BB * MM * WWD) g_mem[i] = DELTA;
    if (i < G4H * 1024) {
        int n = i >> 10, k = i & 1023;
        int h = n >> 2, g = n & 3;
        g_W1p[i] = (k < 512) ? Wih1[(g * 512 + h) * 512 + k]
                             : Whh1[(g * 512 + h) * 512 + (k - 512)];
    }
    if (i < G4H * 512) {
        int n = i >> 9, k = i & 511;
        int h = n >> 2, g = n & 3;
        g_W0p[i] = Whh0[(g * 512 + h) * 512 + k];
    }
    if (i < G4H * 256) {
        int n = i >> 8, k = i & 255;
        int h = n >> 2, g = n & 3;
        g_Wih0p[i] = Wih0[(g * 512 + h) * 512 + k];
    }
    if (i < 512 * 480) {
        int k = i / 480, ii = i - k * 480;
        g_WifT[i] = (ii < IFACE) ? Wif[ii * 512 + k] : 0.f;
    }
    if (i < G4H) {
        int h = i >> 2, g = i & 3;
        g_bp0[i] = bih0[g * 512 + h] + bhh0[g * 512 + h];
        g_bp1[i] = bih1[g * 512 + h] + bhh1[g * 512 + h];
    }
    if (i < BB * HH) {
        g_h0buf[i] = h0in[i];
        g_c0[i] = h0in[i];
        g_c1[i] = h0in[32768 + i];
    }
    if (i < BB * 1024) {
        int b = i >> 10, c = i & 1023;
        if (c >= 512) g_in1[i] = h0in[32768 + b * 512 + (c - 512)];
    }
    if (i < BB * RR * MM) g_rw[i] = DELTA;
    if (i < BB * MM) { g_ww[i] = DELTA; g_usage[i] = 0.f; g_prec[i] = 0.f; }
}

// ---------------- phase A tile: one 64x16 GEMM tile + lstm0 cell ----------
// 256-thread group (tid256), K=512 pipelined, named barrier barid.
// ti<128: lstm0 tile; ti>=128: lstm1 h1-half partial into g_p1h.
__device__ __forceinline__ void tileA(int t, int ti, int tid256, int barid,
                                      const float* __restrict__ h0prev,
                                      float* __restrict__ h0next,
                                      float* __restrict__ in1cur,
                                      float* sbase, float& c0reg)
{
    const int r = tid256 & 63, q = tid256 >> 6;
    const int part = (ti >= 128);
    const int nb = part ? (ti - 128) : ti;
    const int n0 = nb * 16;
    const int a_row = tid256 >> 2, a_kb = (tid256 & 3) * 8;
    const int b_n = tid256 >> 4, b_k2 = (tid256 & 15) * 2;
    float* As = sbase;            // [32][65]
    float* Bs = sbase + 2080;     // [32][20]
    const float* Ap = part ? (in1cur + 512 + a_row * 1024 + a_kb)
                           : (h0prev + a_row * 512 + a_kb);
    const float* Bp = part ? (g_W1p + (n0 + b_n) * 1024 + 512 + b_k2)
                           : (g_W0p + (n0 + b_n) * 512 + b_k2);
    float acc0 = 0.f, acc1 = 0.f, acc2 = 0.f, acc3 = 0.f;

    float4 ra0 = __ldcg((const float4*)Ap);
    float4 ra1 = __ldcg((const float4*)(Ap + 4));
    float rb0 = Bp[0], rb1 = Bp[1];

    #pragma unroll 1
    for (int k0 = 0; k0 < 512; k0 += 32) {
        asm volatile("bar.sync %0, 256;" :: "r"(barid) : "memory");
        As[(a_kb + 0) * 65 + a_row] = ra0.x; As[(a_kb + 1) * 65 + a_row] = ra0.y;
        As[(a_kb + 2) * 65 + a_row] = ra0.z; As[(a_kb + 3) * 65 + a_row] = ra0.w;
        As[(a_kb + 4) * 65 + a_row] = ra1.x; As[(a_kb + 5) * 65 + a_row] = ra1.y;
        As[(a_kb + 6) * 65 + a_row] = ra1.z; As[(a_kb + 7) * 65 + a_row] = ra1.w;
        Bs[b_k2 * 20 + b_n] = rb0; Bs[(b_k2 + 1) * 20 + b_n] = rb1;
        asm volatile("bar.sync %0, 256;" :: "r"(barid) : "memory");
        if (k0 + 32 < 512) {
            ra0 = __ldcg((const float4*)(Ap + k0 + 32));
            ra1 = __ldcg((const float4*)(Ap + k0 + 36));
            rb0 = Bp[k0 + 32]; rb1 = Bp[k0 + 33];
        }
        #pragma unroll
        for (int kk = 0; kk < 32; kk++) {
            float a = As[kk * 65 + r];
            float4 b4 = *(const float4*)&Bs[kk * 20 + q * 4];
            acc0 += a * b4.x; acc1 += a * b4.y; acc2 += a * b4.z; acc3 += a * b4.w;
        }
    }
    int hidx = nb * 4 + q;
    if (part) {
        float4 v; v.x = acc0; v.y = acc1; v.z = acc2; v.w = acc3;
        *(float4*)&g_p1h[r * 2048 + hidx * 4] = v;
    } else {
        float4 xp = *(const float4*)&g_xprojp[((long)(r * TT + t)) * G4H + hidx * 4];
        float gi = acc0 + xp.x, gf = acc1 + xp.y, gg = acc2 + xp.z, go = acc3 + xp.w;
        float c = sigf(gf) * c0reg + sigf(gi) * tanhfast(gg);
        c0reg = c;
        float hh = sigf(go) * tanhfast(c);
        h0next[r * 512 + hidx] = hh;
        in1cur[r * 1024 + hidx] = hh;
    }
}

// ---------------- persistent kernel: all TT steps ----------------
#define MEM_SMEM_FLOATS (256*65 + 4*1024 + 6*256 + 256 + 480 + 512 + 16 + 96 + 512)

__global__ void __launch_bounds__(512) dnc_persistent(const float* __restrict__ bif)
{
    extern __shared__ float sm[];
    const int tid = threadIdx.x;
    const int bx = blockIdx.x;

    // register-resident cell states (block->h mapping is static across t)
    float c0reg = 0.f, c1reg = 0.f;
    {
        int hf = tid >> 8, tid256 = tid & 255;
        int ti = bx * 2 + hf;
        if (ti < 128) c0reg = g_c0[(tid256 & 63) * 512 + ti * 4 + (tid256 >> 6)];
        if (tid < 256) c1reg = g_c1[(tid & 63) * 512 + bx * 4 + (tid >> 6)];
    }

    int bar = 0;
    for (int t = 0; t < TT; t++) {
        const int p = t & 1;
        const float* h0prev = g_h0buf + p * (BB * HH);
        float* h0next = g_h0buf + (p ^ 1) * (BB * HH);
        float* in1cur = g_in1 + p * (BB * 1024);
        float* in1next = g_in1 + (p ^ 1) * (BB * 1024);

        // ---- phase A: 256 tiles (128 lstm0 + 128 p1h), 2 per block ----
        {
            int hf = tid >> 8, tid256 = tid & 255;
            tileA(t, bx * 2 + hf, tid256, 1 + hf, h0prev, h0next, in1cur,
                  sm + hf * 2720, c0reg);
        }
        grid_bar(bar++);

        // ---- phase B: lstm1 (K=512 over h0(t), in-block split-K 2x256) ----
        {
            const int g = tid >> 8, gtid = tid & 255;
            const int r = gtid & 63, q = gtid >> 6;
            const int n0 = bx * 16;
            const int a_row = gtid >> 2, a_kb = (gtid & 3) * 8;
            const int b_n = gtid >> 4, b_k2 = (gtid & 15) * 2;
            float* As = sm + g * 2080;
            float* Bs = sm + 4160 + g * 640;
            float* s_part = sm + 5440;      // 1024 floats
            const float* Ap = in1cur + a_row * 1024 + g * 256 + a_kb;
            const float* Bp = g_W1p + (n0 + b_n) * 1024 + g * 256 + b_k2;
            float acc0 = 0.f, acc1 = 0.f, acc2 = 0.f, acc3 = 0.f;

            float4 ra0 = __ldcg((const float4*)Ap);
            float4 ra1 = __ldcg((const float4*)(Ap + 4));
            float rb0 = Bp[0], rb1 = Bp[1];

            #pragma unroll 1
            for (int k0 = 0; k0 < 256; k0 += 32) {
                __syncthreads();
                As[(a_kb + 0) * 65 + a_row] = ra0.x; As[(a_kb + 1) * 65 + a_row] = ra0.y;
                As[(a_kb + 2) * 65 + a_row] = ra0.z; As[(a_kb + 3) * 65 + a_row] = ra0.w;
                As[(a_kb + 4) * 65 + a_row] = ra1.x; As[(a_kb + 5) * 65 + a_row] = ra1.y;
                As[(a_kb + 6) * 65 + a_row] = ra1.z; As[(a_kb + 7) * 65 + a_row] = ra1.w;
                Bs[b_k2 * 20 + b_n] = rb0; Bs[(b_k2 + 1) * 20 + b_n] = rb1;
                __syncthreads();
                if (k0 + 32 < 256) {
                    ra0 = __ldcg((const float4*)(Ap + k0 + 32));
                    ra1 = __ldcg((const float4*)(Ap + k0 + 36));
                    rb0 = Bp[k0 + 32]; rb1 = Bp[k0 + 33];
                }
                #pragma unroll
                for (int kk = 0; kk < 32; kk++) {
                    float a = As[kk * 65 + r];
                    float4 b4 = *(const float4*)&Bs[kk * 20 + q * 4];
                    acc0 += a * b4.x; acc1 += a * b4.y; acc2 += a * b4.z; acc3 += a * b4.w;
                }
            }
            if (g == 1) {
                s_part[gtid] = acc0; s_part[256 + gtid] = acc1;
                s_part[512 + gtid] = acc2; s_part[768 + gtid] = acc3;
            }
            __syncthreads();
            if (g == 0) {
                acc0 += s_part[gtid]; acc1 += s_part[256 + gtid];
                acc2 += s_part[512 + gtid]; acc3 += s_part[768 + gtid];
                int hidx = bx * 4 + q;
                float4 bi = *(const float4*)&g_bp1[hidx * 4];
                float4 pp = __ldcg((const float4*)&g_p1h[r * 2048 + hidx * 4]);
                float gi = acc0 + pp.x + bi.x, gf = acc1 + pp.y + bi.y;
                float gg = acc2 + pp.z + bi.z, go = acc3 + pp.w + bi.w;
                float c = sigf(gf) * c1reg + sigf(gi) * tanhfast(gg);
                c1reg = c;
                float h1 = sigf(go) * tanhfast(c);
                in1next[r * 1024 + 512 + hidx] = h1;
                float o = fminf(fmaxf(h1, -CLIPV), CLIPV);
                g_outb[r * 512 + hidx] = o;
                g_ys[((long)(r * TT + t)) * NNOUT + hidx] = o;
            }
        }
        grid_bar(bar++);

        // ---- phase C: memory step, blocks 0..63 (one per batch) ----
        if (bx < BB) {
            float* s_mem  = sm;
            float* s_rwo  = s_mem + 256 * 65;
            float* s_rwn  = s_rwo + 1024;
            float* s_fwd  = s_rwn + 1024;
            float* s_bwd  = s_fwd + 1024;
            float* s_ww   = s_bwd + 1024;
            float* s_wwo  = s_ww + 256;
            float* s_prec = s_wwo + 256;
            float* s_alloc= s_prec + 256;
            float* s_wcw  = s_alloc + 256;
            float* s_key  = s_wcw + 256;
            int*   s_idx  = (int*)(s_key + 256);
            float* s_xi   = (float*)(s_idx + 256);
            float* s_red  = s_xi + 480;
            float* s_rm   = s_red + 512;
            float* s_scr  = s_rm + 16;
            float* s_h    = s_scr + 96;

            const int b = bx;
            const int m = tid & 255;
            const int warp = tid >> 5, lane = tid & 31;

            s_h[tid] = __ldcg(&g_outb[b * 512 + tid]);
            for (int i = tid; i < 1024; i += 512) s_rwo[i] = g_rw[b * 1024 + i];
            if (tid < 256) {
                s_wwo[tid]  = g_ww[b * 256 + tid];
                s_prec[tid] = g_prec[b * 256 + tid];
            }
            for (int i = tid; i < MM * WWD; i += 512)
                s_mem[(i >> 6) * 65 + (i & 63)] = g_mem[(long)b * MM * WWD + i];
            __syncthreads();

            if (tid < IFACE) {
                float acc = bif[tid];
                const float* wp = g_WifT + tid;
                #pragma unroll 8
                for (int k = 0; k < 512; k++)
                    acc += wp[k * 480] * s_h[k];
                float v = acc;
                int i = tid;
                if      (i < 256) v = tanhfast(v);
                else if (i < 260) v = splusf(v);
                else if (i < 324) v = tanhfast(v);
                else if (i == 324) v = splusf(v);
                else if (i < 389) v = sigf(v);
                else if (i < 453) v = tanhfast(v);
                else if (i < 459) v = sigf(v);
                s_xi[i] = v;
            }
            __syncthreads();

            if (tid < 4) {
                float a = s_xi[459 + tid * 3], bb2 = s_xi[460 + tid * 3], cc = s_xi[461 + tid * 3];
                float mx = fmaxf(a, fmaxf(bb2, cc));
                float ea = __expf(a - mx), eb = __expf(bb2 - mx), ec = __expf(cc - mx);
                float s = ea + eb + ec;
                s_rm[tid * 3] = __fdividef(ea, s);
                s_rm[tid * 3 + 1] = __fdividef(eb, s);
                s_rm[tid * 3 + 2] = __fdividef(ec, s);
            }

            // usage update
            float u = 0.f;
            if (tid < 256) {
                u = g_usage[b * 256 + m];
                u = u + (1.f - u) * s_wwo[m];
                float psi = 1.f;
                #pragma unroll
                for (int r = 0; r < 4; r++) psi *= 1.f - s_xi[453 + r] * s_rwo[r * 256 + m];
                u *= psi;
                g_usage[b * 256 + m] = u;
            }

            // write content weights (OLD memory)
            float z = -1e30f;
            if (tid < 256) {
                float nk = 0.f, nm = 0.f, dot = 0.f;
                #pragma unroll 8
                for (int w = 0; w < 64; w++) {
                    float kv = s_xi[260 + w];
                    float mv = s_mem[m * 65 + w];
                    nk += kv * kv; nm += mv * mv; dot += mv * kv;
                }
                nk = sqrtf(nk) + DELTA; nm = sqrtf(nm) + DELTA;
                z = __fdividef(dot, nm * nk) * s_xi[324];
            }
            {   // block max / sum over 512 (256 active)
                float v = z;
                #pragma unroll
                for (int o = 16; o > 0; o >>= 1) v = fmaxf(v, __shfl_xor_sync(0xffffffffu, v, o));
                if (lane == 0) s_scr[warp] = v;
                __syncthreads();
                if (tid < 32) {
                    float x = (tid < 16) ? s_scr[tid] : -1e30f;
                    #pragma unroll
                    for (int o = 8; o > 0; o >>= 1) x = fmaxf(x, __shfl_xor_sync(0xffffffffu, x, o));
                    if (tid == 0) s_scr[0] = x;
                }
                __syncthreads();
            }
            float mx2 = s_scr[0];
            __syncthreads();
            float e = (tid < 256) ? __expf(z - mx2) : 0.f;
            {
                float v = e;
                #pragma unroll
                for (int o = 16; o > 0; o >>= 1) v += __shfl_xor_sync(0xffffffffu, v, o);
                if (lane == 0) s_scr[warp] = v;
                __syncthreads();
                if (tid < 32) {
                    float x = (tid < 16) ? s_scr[tid] : 0.f;
                    #pragma unroll
                    for (int o = 8; o > 0; o >>= 1) x += __shfl_xor_sync(0xffffffffu, x, o);
                    if (tid == 0) s_scr[0] = x;
                }
                __syncthreads();
            }
            float ssum = s_scr[0];
            __syncthreads();
            if (tid < 256) s_wcw[m] = __fdividef(e, ssum);

            // allocation: stable ascending bitonic sort
            if (tid < 256) { s_key[m] = DELTA + (1.f - DELTA) * u; s_idx[m] = m; }
            __syncthreads();
            for (int k = 2; k <= 256; k <<= 1) {
                for (int j = k >> 1; j > 0; j >>= 1) {
                    if (tid < 256) {
                        int l = tid ^ j;
                        if (l > tid) {
                            bool up = ((tid & k) == 0);
                            float ki = s_key[tid], kl = s_key[l];
                            int ii = s_idx[tid], il = s_idx[l];
                            bool igt = (ki > kl) || (ki == kl && ii > il);
                            if (igt == up) { s_key[tid] = kl; s_key[l] = ki; s_idx[tid] = il; s_idx[l] = ii; }
                        }
                    }
                    __syncthreads();
                }
            }
            if (tid < 256) s_red[tid] = s_key[tid];
            __syncthreads();
            for (int off = 1; off < 256; off <<= 1) {
                float prev = 1.f;
                if (tid < 256 && tid >= off) prev = s_red[tid - off];
                __syncthreads();
                if (tid < 256) s_red[tid] *= prev;
                __syncthreads();
            }
            if (tid < 256) {
                float excl = (tid == 0) ? 1.f : s_red[tid - 1];
                s_alloc[s_idx[tid]] = (1.f - s_key[tid]) * excl;
            }
            __syncthreads();

            // new write weights
            float wwn = 0.f;
            if (tid < 256) {
                float ag = s_xi[457], wg = s_xi[458];
                wwn = wg * (ag * s_alloc[m] + (1.f - ag) * s_wcw[m]);
                s_ww[m] = wwn;
            }
            {
                float v = wwn;
                #pragma unroll
                for (int o = 16; o > 0; o >>= 1) v += __shfl_xor_sync(0xffffffffu, v, o);
                if (lane == 0) s_scr[warp] = v;
                __syncthreads();
                if (tid < 32) {
                    float x = (tid < 16) ? s_scr[tid] : 0.f;
                    #pragma unroll
                    for (int o = 8; o > 0; o >>= 1) x += __shfl_xor_sync(0xffffffffu, x, o);
                    if (tid == 0) s_scr[0] = x;
                }
                __syncthreads();
            }
            float sumww = s_scr[0];
            __syncthreads();

            // memory erase + write
            {
                int mm2 = tid >> 1, w0 = (tid & 1) * 32;
                float wv = s_ww[mm2];
                #pragma unroll 8
                for (int w = 0; w < 32; w++) {
                    int idx = mm2 * 65 + w0 + w;
                    s_mem[idx] = s_mem[idx] * (1.f - wv * s_xi[325 + w0 + w]) + wv * s_xi[389 + w0 + w];
                }
            }
            __syncthreads();
            for (int i = tid; i < MM * WWD; i += 512)
                g_mem[(long)b * MM * WWD + i] = s_mem[(i >> 6) * 65 + (i & 63)];

            // link row pass: update + fwd
            float* lrow = g_link + (long)b * MM * MM;
            for (int ii = 0; ii < 16; ii++) {
                int i = warp * 16 + ii;
                float wwi = s_ww[i];
                float ps = 1.f - wwi;
                float f0 = 0.f, f1 = 0.f, f2 = 0.f, f3 = 0.f;
                #pragma unroll
                for (int it = 0; it < 2; it++) {
                    int j0 = (it * 32 + lane) * 4;
                    float4 lo = *(float4*)&lrow[i * 256 + j0];
                    float4 wj = *(float4*)&s_ww[j0];
                    float4 pj = *(float4*)&s_prec[j0];
                    float4 ln;
                    ln.x = (ps - wj.x) * lo.x + wwi * pj.x;
                    ln.y = (ps - wj.y) * lo.y + wwi * pj.y;
                    ln.z = (ps - wj.z) * lo.z + wwi * pj.z;
                    ln.w = (ps - wj.w) * lo.w + wwi * pj.w;
                    if (j0 + 0 == i) ln.x = 0.f;
                    if (j0 + 1 == i) ln.y = 0.f;
                    if (j0 + 2 == i) ln.z = 0.f;
                    if (j0 + 3 == i) ln.w = 0.f;
                    *(float4*)&lrow[i * 256 + j0] = ln;
                    float4 r0v = *(float4*)&s_rwo[j0];
                    float4 r1v = *(float4*)&s_rwo[256 + j0];
                    float4 r2v = *(float4*)&s_rwo[512 + j0];
                    float4 r3v = *(float4*)&s_rwo[768 + j0];
                    f0 += ln.x * r0v.x + ln.y * r0v.y + ln.z * r0v.z + ln.w * r0v.w;
                    f1 += ln.x * r1v.x + ln.y * r1v.y + ln.z * r1v.z + ln.w * r1v.w;
                    f2 += ln.x * r2v.x + ln.y * r2v.y + ln.z * r2v.z + ln.w * r2v.w;
                    f3 += ln.x * r3v.x + ln.y * r3v.y + ln.z * r3v.z + ln.w * r3v.w;
                }
                #pragma unroll
                for (int o = 16; o > 0; o >>= 1) {
                    f0 += __shfl_xor_sync(0xffffffffu, f0, o);
                    f1 += __shfl_xor_sync(0xffffffffu, f1, o);
                    f2 += __shfl_xor_sync(0xffffffffu, f2, o);
                    f3 += __shfl_xor_sync(0xffffffffu, f3, o);
                }
                if (lane == 0) {
                    s_fwd[i] = f0; s_fwd[256 + i] = f1; s_fwd[512 + i] = f2; s_fwd[768 + i] = f3;
                }
            }
            __syncthreads();

            // bwd column pass (two-phase smem combine)
            {
                int jb = (warp & 7) * 32 + lane;
                int ibase = (warp >> 3) * 128;
                float b0 = 0.f, b1 = 0.f, b2 = 0.f, b3 = 0.f;
                #pragma unroll 4
                for (int i = 0; i < 128; i++) {
                    float lv = lrow[(ibase + i) * 256 + jb];
                    b0 += s_rwo[ibase + i] * lv;
                    b1 += s_rwo[256 + ibase + i] * lv;
                    b2 += s_rwo[512 + ibase + i] * lv;
                    b3 += s_rwo[768 + ibase + i] * lv;
                }
                if (warp < 8) {
                    s_bwd[jb] = b0; s_bwd[256 + jb] = b1; s_bwd[512 + jb] = b2; s_bwd[768 + jb] = b3;
                }
                __syncthreads();
                if (warp >= 8) {
                    s_bwd[jb] += b0; s_bwd[256 + jb] += b1; s_bwd[512 + jb] += b2; s_bwd[768 + jb] += b3;
                }
                __syncthreads();
            }

            if (tid < 256) {
                g_prec[b * 256 + m] = (1.f - sumww) * s_prec[m] + s_ww[m];
                g_ww[b * 256 + m] = s_ww[m];
            }

            // read content weights (NEW memory), 4 heads
            const int r0 = tid >> 8;
            float nk0 = 0.f, nk1 = 0.f;
            #pragma unroll 8
            for (int w = 0; w < 64; w++) {
                float k0v = s_xi[r0 * 64 + w], k1v = s_xi[(r0 + 2) * 64 + w];
                nk0 += k0v * k0v; nk1 += k1v * k1v;
            }
            nk0 = sqrtf(nk0) + DELTA; nk1 = sqrtf(nk1) + DELTA;
            float nm2 = 0.f, d0 = 0.f, d1 = 0.f;
            #pragma unroll 8
            for (int w = 0; w < 64; w++) {
                float mv = s_mem[m * 65 + w];
                nm2 += mv * mv;
                d0 += mv * s_xi[r0 * 64 + w];
                d1 += mv * s_xi[(r0 + 2) * 64 + w];
            }
            nm2 = sqrtf(nm2) + DELTA;
            float z0 = __fdividef(d0, nm2 * nk0) * s_xi[256 + r0];
            float z1 = __fdividef(d1, nm2 * nk1) * s_xi[256 + r0 + 2];

            {
                float w0 = z0, w1 = z1;
                #pragma unroll
                for (int o = 16; o > 0; o >>= 1) {
                    w0 = fmaxf(w0, __shfl_xor_sync(0xffffffffu, w0, o));
                    w1 = fmaxf(w1, __shfl_xor_sync(0xffffffffu, w1, o));
                }
                if (lane == 0) { s_scr[warp] = w0; s_scr[16 + warp] = w1; }
            }
            __syncthreads();
            if (tid < 32) {
                float v = s_scr[tid];
                v = fmaxf(v, __shfl_xor_sync(0xffffffffu, v, 4, 8));
                v = fmaxf(v, __shfl_xor_sync(0xffffffffu, v, 2, 8));
                v = fmaxf(v, __shfl_xor_sync(0xffffffffu, v, 1, 8));
                if ((tid & 7) == 0) s_scr[32 + (tid >> 3)] = v;
            }
            __syncthreads();
            float e0 = __expf(z0 - s_scr[32 + r0]);
            float e1 = __expf(z1 - s_scr[34 + r0]);
            {
                float w0 = e0, w1 = e1;
                #pragma unroll
                for (int o = 16; o > 0; o >>= 1) {
                    w0 += __shfl_xor_sync(0xffffffffu, w0, o);
                    w1 += __shfl_xor_sync(0xffffffffu, w1, o);
                }
                if (lane == 0) { s_scr[40 + warp] = w0; s_scr[56 + warp] = w1; }
            }
            __syncthreads();
            if (tid < 32) {
                float v = s_scr[40 + tid];
                v += __shfl_xor_sync(0xffffffffu, v, 4, 8);
                v += __shfl_xor_sync(0xffffffffu, v, 2, 8);
                v += __shfl_xor_sync(0xffffffffu, v, 1, 8);
                if ((tid & 7) == 0) s_scr[72 + (tid >> 3)] = v;
            }
            __syncthreads();
            float rc0 = __fdividef(e0, s_scr[72 + r0]);
            float rc1 = __fdividef(e1, s_scr[74 + r0]);

            {
                int rA = r0, rB = r0 + 2;
                float rnA = s_rm[rA * 3] * s_bwd[rA * 256 + m]
                          + s_rm[rA * 3 + 1] * s_fwd[rA * 256 + m]
                          + s_rm[rA * 3 + 2] * rc0;
                float rnB = s_rm[rB * 3] * s_bwd[rB * 256 + m]
                          + s_rm[rB * 3 + 1] * s_fwd[rB * 256 + m]
                          + s_rm[rB * 3 + 2] * rc1;
                s_rwn[rA * 256 + m] = rnA;
                s_rwn[rB * 256 + m] = rnB;
                g_rw[b * 1024 + rA * 256 + m] = rnA;
                g_rw[b * 1024 + rB * 256 + m] = rnB;
            }
            __syncthreads();

            {
                int o = tid & 255, half = tid >> 8;
                int r = o >> 6, w = o & 63;
                float acc = 0.f;
                int mstart = half * 128;
                #pragma unroll 4
                for (int mm2 = mstart; mm2 < mstart + 128; mm2++)
                    acc += s_rwn[r * 256 + mm2] * s_mem[mm2 * 65 + w];
                s_red[tid] = acc;
            }
            __syncthreads();
            if (tid < 256)
                g_ys[((long)(b * TT + t)) * NNOUT + 512 + tid] = s_red[tid] + s_red[tid + 256];
        }
        grid_bar(bar++);
    }
}

// ---------------- host orchestration ----------------
extern "C" void kernel_launch(void* const* d_in, const int* in_sizes, int n_in,
                              void* d_out, int out_size)
{
    const float* x    = (const float*)d_in[0];
    const float* h0   = (const float*)d_in[1];
    const float* Wih0 = (const float*)d_in[2];
    const float* Whh0 = (const float*)d_in[3];
    const float* bih0 = (const float*)d_in[4];
    const float* bhh0 = (const float*)d_in[5];
    const float* Wih1 = (const float*)d_in[6];
    const float* Whh1 = (const float*)d_in[7];
    const float* bih1 = (const float*)d_in[8];
    const float* bhh1 = (const float*)d_in[9];
    const float* Wif  = (const float*)d_in[10];
    const float* bif  = (const float*)d_in[11];
    const float* Wout = (const float*)d_in[12];
    const float* bout = (const float*)d_in[13];
    float* out = (float*)d_out;
    (void)in_sizes; (void)n_in; (void)out_size;

    (void)cudaFuncSetAttribute(dnc_persistent, cudaFuncAttributeMaxDynamicSharedMemorySize,
                               MEM_SMEM_FLOATS * 4);

    float *p_ys, *p_Wih0p, *p_bp0, *p_xprojp;
    cudaGetSymbolAddress((void**)&p_xprojp, g_xprojp);
    cudaGetSymbolAddress((void**)&p_ys, g_ys);
    cudaGetSymbolAddress((void**)&p_Wih0p, g_Wih0p);
    cudaGetSymbolAddress((void**)&p_bp0, g_bp0);

    init_kernel<<<16384, 256>>>(h0, Wih0, Whh0, bih0, bhh0,
                                Wih1, Whh1, bih1, bhh1, Wif);

    // xprojp: (B*T,256) @ Wih0p^T + bp0 -> [b*T+t][4h+g]
    gemm_bt<<<dim3(G4H / 32, (BB * TT) / 64, 1), 256>>>(
        x, 256, p_Wih0p, 256, p_xprojp, G4H, G4H, 256, p_bp0, 0);

    // whole recurrence in one persistent kernel
    dnc_persistent<<<NBLK, 512, MEM_SMEM_FLOATS * 4>>>(bif);

    // final: out = tanh(ys) @ Wout^T + bout (tanh folded into A-load)
    gemm_bt<<<dim3(256 / 32, (BB * TT) / 64, 1), 256>>>(
        p_ys, NNOUT, Wout, NNOUT, out, 256, 256, NNOUT, bout, 1);
}

// round 17
// speedup vs baseline: 1.6065x; 1.6065x over previous
#include <cuda_runtime.h>
#include <math.h>

// ---------------- problem constants ----------------
#define BB 64
#define TT 32
#define HH 512
#define MM 256
#define WWD 64
#define RR 4
#define IFACE 471
#define G4H 2048
#define NNOUT 768
#define CLIPV 20.0f
#define DELTA 1e-6f

// ---------------- device state ----------------
__device__ float g_xprojp[BB*TT*G4H];   // permuted x-projection incl. biases, [b*T+t][4h+g]
__device__ float g_p1h[BB*G4H];         // lstm1 partial: W1p[:,512:] @ h1_old
__device__ float g_h0buf[2*BB*HH];      // parity buffers for h0
__device__ float g_in1[2*BB*1024];      // parity buffers for [h0 | h1]
__device__ float g_c0[BB*HH];
__device__ float g_c1[BB*HH];
__device__ float g_outb[BB*HH];
__device__ float g_mem[BB*MM*WWD];
__device__ float g_link[BB*MM*MM];
__device__ float g_prec[BB*MM];
__device__ float g_rw[BB*RR*MM];
__device__ float g_ww[BB*MM];
__device__ float g_usage[BB*MM];
__device__ float g_ys[BB*TT*NNOUT];
__device__ float g_W0p[G4H*512];        // permuted Whh0  (row n'=4h+g)
__device__ float g_Wih0p[G4H*256];      // permuted Wih0[:, :256]
__device__ float g_W1p[G4H*1024];       // permuted [Wih1 | Whh1]
__device__ float g_WifT[512*480];       // transposed Wif: [k][i], i padded to 480
__device__ float g_bp0[G4H];
__device__ float g_bp1[G4H];

// ---------------- fast-math helpers ----------------
__device__ __forceinline__ float sigf(float x) {
    return __fdividef(1.f, 1.f + __expf(-x));
}
__device__ __forceinline__ float tanhfast(float x) {
    float e = __expf(-2.f * fabsf(x));
    float r = __fdividef(1.f - e, 1.f + e);
    return copysignf(r, x);
}
__device__ __forceinline__ float splusf(float x) {
    return fmaxf(x, 0.f) + log1pf(__expf(-fabsf(x)));
}

// ---------------- generic C = A * B^T (B row-major [N][K]) ----------------
#define TKC 16
__global__ void __launch_bounds__(256) gemm_bt(
                        const float* __restrict__ A, int lda,
                        const float* __restrict__ Bw, int ldb,
                        float* __restrict__ C, int ldc,
                        int N, int Klen,
                        const float* __restrict__ bias0,
                        int tanhA)
{
    __shared__ float As[TKC][68];
    __shared__ __align__(16) float Bs[TKC][34];

    const int tid = threadIdx.x;
    const int tx = tid & 15;
    const int ty = tid >> 4;
    const int row0 = blockIdx.y * 64;
    const int n0 = blockIdx.x * 32;

    float acc[4][2] = {};

    const int la_m = tid >> 2;
    const int la_k = (tid & 3) * 4;
    const int lb_n = tid >> 3;
    const int lb_k = (tid & 7) * 2;

    const float* Ab = A + (long)(row0 + la_m) * lda + la_k;
    const bool bvalid = (n0 + lb_n) < N;
    const float* Bb = Bw + (long)(n0 + lb_n) * ldb + lb_k;

    float a0 = Ab[0], a1 = Ab[1], a2 = Ab[2], a3 = Ab[3];
    float b0 = 0.f, b1 = 0.f;
    if (bvalid) { b0 = Bb[0]; b1 = Bb[1]; }

    for (int k0 = 0; k0 < Klen; k0 += TKC) {
        float sa0 = a0, sa1 = a1, sa2 = a2, sa3 = a3;
        if (tanhA) { sa0 = tanhfast(sa0); sa1 = tanhfast(sa1);
                     sa2 = tanhfast(sa2); sa3 = tanhfast(sa3); }
        __syncthreads();
        As[la_k + 0][la_m] = sa0; As[la_k + 1][la_m] = sa1;
        As[la_k + 2][la_m] = sa2; As[la_k + 3][la_m] = sa3;
        Bs[lb_k][lb_n] = b0; Bs[lb_k + 1][lb_n] = b1;
        __syncthreads();
        if (k0 + TKC < Klen) {
            a0 = Ab[k0 + TKC + 0]; a1 = Ab[k0 + TKC + 1];
            a2 = Ab[k0 + TKC + 2]; a3 = Ab[k0 + TKC + 3];
            if (bvalid) { b0 = Bb[k0 + TKC]; b1 = Bb[k0 + TKC + 1]; }
        }
        #pragma unroll
        for (int kk = 0; kk < TKC; kk++) {
            float4 av = *(const float4*)&As[kk][ty * 4];
            float2 bv = *(const float2*)&Bs[kk][tx * 2];
            acc[0][0] += av.x * bv.x; acc[0][1] += av.x * bv.y;
            acc[1][0] += av.y * bv.x; acc[1][1] += av.y * bv.y;
            acc[2][0] += av.z * bv.x; acc[2][1] += av.z * bv.y;
            acc[3][0] += av.w * bv.x; acc[3][1] += av.w * bv.y;
        }
    }
    #pragma unroll
    for (int i = 0; i < 4; i++) {
        int m = row0 + ty * 4 + i;
        #pragma unroll
        for (int j = 0; j < 2; j++) {
            int n = n0 + tx * 2 + j;
            if (n < N) {
                float v = acc[i][j];
                if (bias0) v += bias0[n];
                C[(long)m * ldc + n] = v;
            }
        }
    }
}

// ---------------- init: permute weights + init state ----------------
__global__ void __launch_bounds__(256) init_kernel(
                            const float* __restrict__ h0in,
                            const float* __restrict__ Wih0,
                            const float* __restrict__ Whh0,
                            const float* __restrict__ bih0,
                            const float* __restrict__ bhh0,
                            const float* __restrict__ Wih1,
                            const float* __restrict__ Whh1,
                            const float* __restrict__ bih1,
                            const float* __restrict__ bhh1,
                            const float* __restrict__ Wif)
{
    int i = blockIdx.x * 256 + threadIdx.x;
    if (i < BB * MM * MM) g_link[i] = 0.f;
    if (i < BB * MM * WWD) g_mem[i] = DELTA;
    if (i < G4H * 1024) {
        int n = i >> 10, k = i & 1023;
        int h = n >> 2, g = n & 3;
        g_W1p[i] = (k < 512) ? Wih1[(g * 512 + h) * 512 + k]
                             : Whh1[(g * 512 + h) * 512 + (k - 512)];
    }
    if (i < G4H * 512) {
        int n = i >> 9, k = i & 511;
        int h = n >> 2, g = n & 3;
        g_W0p[i] = Whh0[(g * 512 + h) * 512 + k];
    }
    if (i < G4H * 256) {
        int n = i >> 8, k = i & 255;
        int h = n >> 2, g = n & 3;
        g_Wih0p[i] = Wih0[(g * 512 + h) * 512 + k];
    }
    if (i < 512 * 480) {
        int k = i / 480, ii = i - k * 480;
        g_WifT[i] = (ii < IFACE) ? Wif[ii * 512 + k] : 0.f;
    }
    if (i < G4H) {
        int h = i >> 2, g = i & 3;
        g_bp0[i] = bih0[g * 512 + h] + bhh0[g * 512 + h];
        g_bp1[i] = bih1[g * 512 + h] + bhh1[g * 512 + h];
    }
    if (i < BB * HH) {
        g_h0buf[i] = h0in[i];
        g_c0[i] = h0in[i];
        g_c1[i] = h0in[32768 + i];
    }
    if (i < BB * 1024) {
        int b = i >> 10, c = i & 1023;
        if (c >= 512) g_in1[i] = h0in[32768 + b * 512 + (c - 512)];
    }
    if (i < BB * RR * MM) g_rw[i] = DELTA;
    if (i < BB * MM) { g_ww[i] = DELTA; g_usage[i] = 0.f; g_prec[i] = 0.f; }
}

// ---------------- kernel A: lstm0 (blocks 0..127) + lstm1 h1-half partial
//  (blocks 128..255). K=512, double-buffered smem: ONE barrier per 32-K tile,
//  loads issued 2 tiles ahead. 64x16 tile, 256 threads. ----
__global__ void __launch_bounds__(256) stageA_kernel(
                             int t, const float* __restrict__ h0prev,
                             float* __restrict__ h0next, float* __restrict__ in1cur)
{
    __shared__ float As[2][32][65];
    __shared__ __align__(16) float Bs[2][32][20];
    const int tid = threadIdx.x;
    const int r = tid & 63, q = tid >> 6;
    const int bx = blockIdx.x;
    const int part = (bx >= 128);
    const int nb = part ? (bx - 128) : bx;
    const int n0 = nb * 16;
    const int a_row = tid >> 2, a_kb = (tid & 3) * 8;
    const int b_n = tid >> 4, b_k2 = (tid & 15) * 2;

    const float* Ap = part ? (in1cur + 512 + a_row * 1024 + a_kb)
                           : (h0prev + a_row * 512 + a_kb);
    const float* Bp = part ? (g_W1p + (n0 + b_n) * 1024 + 512 + b_k2)
                           : (g_W0p + (n0 + b_n) * 512 + b_k2);
    float acc0 = 0.f, acc1 = 0.f, acc2 = 0.f, acc3 = 0.f;

    // prologue: tile0 -> buf0, then preload tile1 regs
    float4 ra0 = *(const float4*)(Ap);
    float4 ra1 = *(const float4*)(Ap + 4);
    float rb0 = Bp[0], rb1 = Bp[1];
    As[0][a_kb + 0][a_row] = ra0.x; As[0][a_kb + 1][a_row] = ra0.y;
    As[0][a_kb + 2][a_row] = ra0.z; As[0][a_kb + 3][a_row] = ra0.w;
    As[0][a_kb + 4][a_row] = ra1.x; As[0][a_kb + 5][a_row] = ra1.y;
    As[0][a_kb + 6][a_row] = ra1.z; As[0][a_kb + 7][a_row] = ra1.w;
    Bs[0][b_k2][b_n] = rb0; Bs[0][b_k2 + 1][b_n] = rb1;
    ra0 = *(const float4*)(Ap + 32);
    ra1 = *(const float4*)(Ap + 36);
    rb0 = Bp[32]; rb1 = Bp[33];
    __syncthreads();

    #pragma unroll 1
    for (int i = 0; i < 16; i++) {
        const int cur = i & 1;
        if (i) __syncthreads();
        if (i + 1 < 16) {
            const int nx = cur ^ 1;
            As[nx][a_kb + 0][a_row] = ra0.x; As[nx][a_kb + 1][a_row] = ra0.y;
            As[nx][a_kb + 2][a_row] = ra0.z; As[nx][a_kb + 3][a_row] = ra0.w;
            As[nx][a_kb + 4][a_row] = ra1.x; As[nx][a_kb + 5][a_row] = ra1.y;
            As[nx][a_kb + 6][a_row] = ra1.z; As[nx][a_kb + 7][a_row] = ra1.w;
            Bs[nx][b_k2][b_n] = rb0; Bs[nx][b_k2 + 1][b_n] = rb1;
        }
        if (i + 2 < 16) {
            ra0 = *(const float4*)(Ap + (i + 2) * 32);
            ra1 = *(const float4*)(Ap + (i + 2) * 32 + 4);
            rb0 = Bp[(i + 2) * 32]; rb1 = Bp[(i + 2) * 32 + 1];
        }
        #pragma unroll
        for (int kk = 0; kk < 32; kk++) {
            float a = As[cur][kk][r];
            float4 b4 = *(const float4*)&Bs[cur][kk][q * 4];
            acc0 += a * b4.x; acc1 += a * b4.y; acc2 += a * b4.z; acc3 += a * b4.w;
        }
    }
    int h = nb * 4 + q;
    if (part) {
        float4 v; v.x = acc0; v.y = acc1; v.z = acc2; v.w = acc3;
        *(float4*)&g_p1h[r * 2048 + h * 4] = v;
    } else {
        float4 xp = *(const float4*)&g_xprojp[((long)(r * TT + t)) * G4H + h * 4];
        float gi = acc0 + xp.x, gf = acc1 + xp.y, gg = acc2 + xp.z, go = acc3 + xp.w;
        float c = sigf(gf) * g_c0[r * 512 + h] + sigf(gi) * tanhfast(gg);
        g_c0[r * 512 + h] = c;
        float hh = sigf(go) * tanhfast(c);
        h0next[r * 512 + h] = hh;
        in1cur[r * 1024 + h] = hh;
    }
}

// ---------------- lstm1': K=512 over h0(t), + g_p1h partial; same pipeline ----
__global__ void __launch_bounds__(256) lstm1_kernel(
                             int t, const float* __restrict__ A,
                             float* __restrict__ in1next)
{
    __shared__ float As[2][32][65];
    __shared__ __align__(16) float Bs[2][32][20];
    const int tid = threadIdx.x;
    const int r = tid & 63, q = tid >> 6;
    const int n0 = blockIdx.x * 16;
    const int a_row = tid >> 2, a_kb = (tid & 3) * 8;
    const int b_n = tid >> 4, b_k2 = (tid & 15) * 2;
    const float* Ap = A + a_row * 1024 + a_kb;            // h0(t) half
    const float* Bp = g_W1p + (n0 + b_n) * 1024 + b_k2;   // first 512 cols
    float acc0 = 0.f, acc1 = 0.f, acc2 = 0.f, acc3 = 0.f;

    float4 ra0 = *(const float4*)(Ap);
    float4 ra1 = *(const float4*)(Ap + 4);
    float rb0 = Bp[0], rb1 = Bp[1];
    As[0][a_kb + 0][a_row] = ra0.x; As[0][a_kb + 1][a_row] = ra0.y;
    As[0][a_kb + 2][a_row] = ra0.z; As[0][a_kb + 3][a_row] = ra0.w;
    As[0][a_kb + 4][a_row] = ra1.x; As[0][a_kb + 5][a_row] = ra1.y;
    As[0][a_kb + 6][a_row] = ra1.z; As[0][a_kb + 7][a_row] = ra1.w;
    Bs[0][b_k2][b_n] = rb0; Bs[0][b_k2 + 1][b_n] = rb1;
    ra0 = *(const float4*)(Ap + 32);
    ra1 = *(const float4*)(Ap + 36);
    rb0 = Bp[32]; rb1 = Bp[33];
    __syncthreads();

    #pragma unroll 1
    for (int i = 0; i < 16; i++) {
        const int cur = i & 1;
        if (i) __syncthreads();
        if (i + 1 < 16) {
            const int nx = cur ^ 1;
            As[nx][a_kb + 0][a_row] = ra0.x; As[nx][a_kb + 1][a_row] = ra0.y;
            As[nx][a_kb + 2][a_row] = ra0.z; As[nx][a_kb + 3][a_row] = ra0.w;
            As[nx][a_kb + 4][a_row] = ra1.x; As[nx][a_kb + 5][a_row] = ra1.y;
            As[nx][a_kb + 6][a_row] = ra1.z; As[nx][a_kb + 7][a_row] = ra1.w;
            Bs[nx][b_k2][b_n] = rb0; Bs[nx][b_k2 + 1][b_n] = rb1;
        }
        if (i + 2 < 16) {
            ra0 = *(const float4*)(Ap + (i + 2) * 32);
            ra1 = *(const float4*)(Ap + (i + 2) * 32 + 4);
            rb0 = Bp[(i + 2) * 32]; rb1 = Bp[(i + 2) * 32 + 1];
        }
        #pragma unroll
        for (int kk = 0; kk < 32; kk++) {
            float a = As[cur][kk][r];
            float4 b4 = *(const float4*)&Bs[cur][kk][q * 4];
            acc0 += a * b4.x; acc1 += a * b4.y; acc2 += a * b4.z; acc3 += a * b4.w;
        }
    }
    int h = blockIdx.x * 4 + q;
    float4 bi = *(const float4*)&g_bp1[h * 4];
    float4 pp = *(const float4*)&g_p1h[r * 2048 + h * 4];
    float gi = acc0 + pp.x + bi.x, gf = acc1 + pp.y + bi.y;
    float gg = acc2 + pp.z + bi.z, go = acc3 + pp.w + bi.w;
    float c = sigf(gf) * g_c1[r * 512 + h] + sigf(gi) * tanhfast(gg);
    g_c1[r * 512 + h] = c;
    float h1 = sigf(go) * tanhfast(c);
    in1next[r * 1024 + 512 + h] = h1;
    float o = fminf(fmaxf(h1, -CLIPV), CLIPV);
    g_outb[r * 512 + h] = o;
    g_ys[((long)(r * TT + t)) * NNOUT + h] = o;
}

// ---------------- memory step: one block (512 thr) per batch ----------------
// Also computes xi = Wif @ outb[b] + bif in-kernel (coalesced over WifT).
#define MEM_SMEM_FLOATS (256*65 + 4*1024 + 6*256 + 256 + 480 + 512 + 16 + 96 + 512)

__global__ void __launch_bounds__(512) mem_kernel(int t, const float* __restrict__ bif)
{
    extern __shared__ float sm[];
    float* s_mem  = sm;                     // 256*65
    float* s_rwo  = s_mem + 256 * 65;       // 1024
    float* s_rwn  = s_rwo + 1024;           // 1024
    float* s_fwd  = s_rwn + 1024;           // 1024
    float* s_bwd  = s_fwd + 1024;           // 1024
    float* s_ww   = s_bwd + 1024;           // 256
    float* s_wwo  = s_ww + 256;
    float* s_prec = s_wwo + 256;
    float* s_alloc= s_prec + 256;
    float* s_wcw  = s_alloc + 256;
    float* s_key  = s_wcw + 256;
    int*   s_idx  = (int*)(s_key + 256);    // 256
    float* s_xi   = (float*)(s_idx + 256);  // 480
    float* s_red  = s_xi + 480;             // 512
    float* s_rm   = s_red + 512;            // 16
    float* s_scr  = s_rm + 16;              // 96
    float* s_h    = s_scr + 96;             // 512

    const int tid = threadIdx.x;
    const int b = blockIdx.x;
    const int m = tid & 255;
    const int warp = tid >> 5, lane = tid & 31;

    // ---- load controller output, compute xi = WifT^T h + bif, activations ----
    s_h[tid] = g_outb[b * 512 + tid];
    for (int i = tid; i < 1024; i += 512) s_rwo[i] = g_rw[b * 1024 + i];
    if (tid < 256) {
        s_wwo[tid]  = g_ww[b * 256 + tid];
        s_prec[tid] = g_prec[b * 256 + tid];
    }
    for (int i = tid; i < MM * WWD; i += 512)
        s_mem[(i >> 6) * 65 + (i & 63)] = g_mem[(long)b * MM * WWD + i];
    __syncthreads();

    if (tid < IFACE) {
        float acc = bif[tid];
        const float* wp = g_WifT + tid;
        #pragma unroll 8
        for (int k = 0; k < 512; k++)
            acc += wp[k * 480] * s_h[k];
        float v = acc;
        int i = tid;
        if      (i < 256) v = tanhfast(v);
        else if (i < 260) v = splusf(v);
        else if (i < 324) v = tanhfast(v);
        else if (i == 324) v = splusf(v);
        else if (i < 389) v = sigf(v);
        else if (i < 453) v = tanhfast(v);
        else if (i < 459) v = sigf(v);
        s_xi[i] = v;
    }
    __syncthreads();

    if (tid < 4) {
        float a = s_xi[459 + tid * 3], bb2 = s_xi[460 + tid * 3], cc = s_xi[461 + tid * 3];
        float mx = fmaxf(a, fmaxf(bb2, cc));
        float ea = __expf(a - mx), eb = __expf(bb2 - mx), ec = __expf(cc - mx);
        float s = ea + eb + ec;
        s_rm[tid * 3] = __fdividef(ea, s);
        s_rm[tid * 3 + 1] = __fdividef(eb, s);
        s_rm[tid * 3 + 2] = __fdividef(ec, s);
    }

    // ---- usage update (old ww, old rw) ----
    float u = 0.f;
    if (tid < 256) {
        u = g_usage[b * 256 + m];
        u = u + (1.f - u) * s_wwo[m];
        float psi = 1.f;
        #pragma unroll
        for (int r = 0; r < 4; r++) psi *= 1.f - s_xi[453 + r] * s_rwo[r * 256 + m];
        u *= psi;
        g_usage[b * 256 + m] = u;
    }

    // ---- write content weights (OLD memory) ----
    float z = -1e30f;
    if (tid < 256) {
        float nk = 0.f, nm = 0.f, dot = 0.f;
        #pragma unroll 8
        for (int w = 0; w < 64; w++) {
            float kv = s_xi[260 + w];
            float mv = s_mem[m * 65 + w];
            nk += kv * kv; nm += mv * mv; dot += mv * kv;
        }
        nk = sqrtf(nk) + DELTA; nm = sqrtf(nm) + DELTA;
        z = __fdividef(dot, nm * nk) * s_xi[324];
    }
    {
        float v = z;
        #pragma unroll
        for (int o = 16; o > 0; o >>= 1) v = fmaxf(v, __shfl_xor_sync(0xffffffffu, v, o));
        if (lane == 0) s_scr[warp] = v;
        __syncthreads();
        if (tid < 32) {
            float x = (tid < 16) ? s_scr[tid] : -1e30f;
            #pragma unroll
            for (int o = 8; o > 0; o >>= 1) x = fmaxf(x, __shfl_xor_sync(0xffffffffu, x, o));
            if (tid == 0) s_scr[0] = x;
        }
        __syncthreads();
    }
    float mx2 = s_scr[0];
    __syncthreads();
    float e = (tid < 256) ? __expf(z - mx2) : 0.f;
    {
        float v = e;
        #pragma unroll
        for (int o = 16; o > 0; o >>= 1) v += __shfl_xor_sync(0xffffffffu, v, o);
        if (lane == 0) s_scr[warp] = v;
        __syncthreads();
        if (tid < 32) {
            float x = (tid < 16) ? s_scr[tid] : 0.f;
            #pragma unroll
            for (int o = 8; o > 0; o >>= 1) x += __shfl_xor_sync(0xffffffffu, x, o);
            if (tid == 0) s_scr[0] = x;
        }
        __syncthreads();
    }
    float ssum = s_scr[0];
    __syncthreads();
    if (tid < 256) s_wcw[m] = __fdividef(e, ssum);

    // ---- allocation: stable ascending bitonic sort of u' ----
    if (tid < 256) { s_key[m] = DELTA + (1.f - DELTA) * u; s_idx[m] = m; }
    __syncthreads();
    for (int k = 2; k <= 256; k <<= 1) {
        for (int j = k >> 1; j > 0; j >>= 1) {
            if (tid < 256) {
                int l = tid ^ j;
                if (l > tid) {
                    bool up = ((tid & k) == 0);
                    float ki = s_key[tid], kl = s_key[l];
                    int ii = s_idx[tid], il = s_idx[l];
                    bool igt = (ki > kl) || (ki == kl && ii > il);
                    if (igt == up) { s_key[tid] = kl; s_key[l] = ki; s_idx[tid] = il; s_idx[l] = ii; }
                }
            }
            __syncthreads();
        }
    }
    if (tid < 256) s_red[tid] = s_key[tid];
    __syncthreads();
    for (int off = 1; off < 256; off <<= 1) {
        float prev = 1.f;
        if (tid < 256 && tid >= off) prev = s_red[tid - off];
        __syncthreads();
        if (tid < 256) s_red[tid] *= prev;
        __syncthreads();
    }
    if (tid < 256) {
        float excl = (tid == 0) ? 1.f : s_red[tid - 1];
        s_alloc[s_idx[tid]] = (1.f - s_key[tid]) * excl;
    }
    __syncthreads();

    // ---- new write weights ----
    float wwn = 0.f;
    if (tid < 256) {
        float ag = s_xi[457], wg = s_xi[458];
        wwn = wg * (ag * s_alloc[m] + (1.f - ag) * s_wcw[m]);
        s_ww[m] = wwn;
    }
    {
        float v = wwn;
        #pragma unroll
        for (int o = 16; o > 0; o >>= 1) v += __shfl_xor_sync(0xffffffffu, v, o);
        if (lane == 0) s_scr[warp] = v;
        __syncthreads();
        if (tid < 32) {
            float x = (tid < 16) ? s_scr[tid] : 0.f;
            #pragma unroll
            for (int o = 8; o > 0; o >>= 1) x += __shfl_xor_sync(0xffffffffu, x, o);
            if (tid == 0) s_scr[0] = x;
        }
        __syncthreads();
    }
    float sumww = s_scr[0];
    __syncthreads();

    // ---- memory erase + write ----
    {
        int mm2 = tid >> 1, w0 = (tid & 1) * 32;
        float wv = s_ww[mm2];
        #pragma unroll 8
        for (int w = 0; w < 32; w++) {
            int idx = mm2 * 65 + w0 + w;
            s_mem[idx] = s_mem[idx] * (1.f - wv * s_xi[325 + w0 + w]) + wv * s_xi[389 + w0 + w];
        }
    }
    __syncthreads();
    for (int i = tid; i < MM * WWD; i += 512)
        g_mem[(long)b * MM * WWD + i] = s_mem[(i >> 6) * 65 + (i & 63)];

    // ---- link row pass: update + fwd (16 warps x 16 rows) ----
    float* lrow = g_link + (long)b * MM * MM;
    for (int ii = 0; ii < 16; ii++) {
        int i = warp * 16 + ii;
        float wwi = s_ww[i];
        float ps = 1.f - wwi;
        float f0 = 0.f, f1 = 0.f, f2 = 0.f, f3 = 0.f;
        #pragma unroll
        for (int it = 0; it < 2; it++) {
            int j0 = (it * 32 + lane) * 4;
            float4 lo = *(float4*)&lrow[i * 256 + j0];
            float4 wj = *(float4*)&s_ww[j0];
            float4 pj = *(float4*)&s_prec[j0];
            float4 ln;
            ln.x = (ps - wj.x) * lo.x + wwi * pj.x;
            ln.y = (ps - wj.y) * lo.y + wwi * pj.y;
            ln.z = (ps - wj.z) * lo.z + wwi * pj.z;
            ln.w = (ps - wj.w) * lo.w + wwi * pj.w;
            if (j0 + 0 == i) ln.x = 0.f;
            if (j0 + 1 == i) ln.y = 0.f;
            if (j0 + 2 == i) ln.z = 0.f;
            if (j0 + 3 == i) ln.w = 0.f;
            *(float4*)&lrow[i * 256 + j0] = ln;
            float4 r0v = *(float4*)&s_rwo[j0];
            float4 r1v = *(float4*)&s_rwo[256 + j0];
            float4 r2v = *(float4*)&s_rwo[512 + j0];
            float4 r3v = *(float4*)&s_rwo[768 + j0];
            f0 += ln.x * r0v.x + ln.y * r0v.y + ln.z * r0v.z + ln.w * r0v.w;
            f1 += ln.x * r1v.x + ln.y * r1v.y + ln.z * r1v.z + ln.w * r1v.w;
            f2 += ln.x * r2v.x + ln.y * r2v.y + ln.z * r2v.z + ln.w * r2v.w;
            f3 += ln.x * r3v.x + ln.y * r3v.y + ln.z * r3v.z + ln.w * r3v.w;
        }
        #pragma unroll
        for (int o = 16; o > 0; o >>= 1) {
            f0 += __shfl_xor_sync(0xffffffffu, f0, o);
            f1 += __shfl_xor_sync(0xffffffffu, f1, o);
            f2 += __shfl_xor_sync(0xffffffffu, f2, o);
            f3 += __shfl_xor_sync(0xffffffffu, f3, o);
        }
        if (lane == 0) {
            s_fwd[i] = f0; s_fwd[256 + i] = f1; s_fwd[512 + i] = f2; s_fwd[768 + i] = f3;
        }
    }
    __syncthreads();

    // ---- bwd column pass over NEW link (two-phase smem combine, no atomics) ----
    {
        int jb = (warp & 7) * 32 + lane;
        int ibase = (warp >> 3) * 128;
        float b0 = 0.f, b1 = 0.f, b2 = 0.f, b3 = 0.f;
        #pragma unroll 4
        for (int i = 0; i < 128; i++) {
            float lv = lrow[(ibase + i) * 256 + jb];
            b0 += s_rwo[ibase + i] * lv;
            b1 += s_rwo[256 + ibase + i] * lv;
            b2 += s_rwo[512 + ibase + i] * lv;
            b3 += s_rwo[768 + ibase + i] * lv;
        }
        if (warp < 8) {
            s_bwd[jb] = b0; s_bwd[256 + jb] = b1; s_bwd[512 + jb] = b2; s_bwd[768 + jb] = b3;
        }
        __syncthreads();
        if (warp >= 8) {
            s_bwd[jb] += b0; s_bwd[256 + jb] += b1; s_bwd[512 + jb] += b2; s_bwd[768 + jb] += b3;
        }
        __syncthreads();
    }

    // ---- precedence + ww stores ----
    if (tid < 256) {
        g_prec[b * 256 + m] = (1.f - sumww) * s_prec[m] + s_ww[m];
        g_ww[b * 256 + m] = s_ww[m];
    }

    // ---- read content weights (NEW memory), 4 heads in parallel ----
    const int r0 = tid >> 8;
    float nk0 = 0.f, nk1 = 0.f;
    #pragma unroll 8
    for (int w = 0; w < 64; w++) {
        float k0v = s_xi[r0 * 64 + w], k1v = s_xi[(r0 + 2) * 64 + w];
        nk0 += k0v * k0v; nk1 += k1v * k1v;
    }
    nk0 = sqrtf(nk0) + DELTA; nk1 = sqrtf(nk1) + DELTA;
    float nm2 = 0.f, d0 = 0.f, d1 = 0.f;
    #pragma unroll 8
    for (int w = 0; w < 64; w++) {
        float mv = s_mem[m * 65 + w];
        nm2 += mv * mv;
        d0 += mv * s_xi[r0 * 64 + w];
        d1 += mv * s_xi[(r0 + 2) * 64 + w];
    }
    nm2 = sqrtf(nm2) + DELTA;
    float z0 = __fdividef(d0, nm2 * nk0) * s_xi[256 + r0];
    float z1 = __fdividef(d1, nm2 * nk1) * s_xi[256 + r0 + 2];

    {
        float w0 = z0, w1 = z1;
        #pragma unroll
        for (int o = 16; o > 0; o >>= 1) {
            w0 = fmaxf(w0, __shfl_xor_sync(0xffffffffu, w0, o));
            w1 = fmaxf(w1, __shfl_xor_sync(0xffffffffu, w1, o));
        }
        if (lane == 0) { s_scr[warp] = w0; s_scr[16 + warp] = w1; }
    }
    __syncthreads();
    if (tid < 32) {
        float v = s_scr[tid];
        v = fmaxf(v, __shfl_xor_sync(0xffffffffu, v, 4, 8));
        v = fmaxf(v, __shfl_xor_sync(0xffffffffu, v, 2, 8));
        v = fmaxf(v, __shfl_xor_sync(0xffffffffu, v, 1, 8));
        if ((tid & 7) == 0) s_scr[32 + (tid >> 3)] = v;
    }
    __syncthreads();
    float e0 = __expf(z0 - s_scr[32 + r0]);
    float e1 = __expf(z1 - s_scr[34 + r0]);
    {
        float w0 = e0, w1 = e1;
        #pragma unroll
        for (int o = 16; o > 0; o >>= 1) {
            w0 += __shfl_xor_sync(0xffffffffu, w0, o);
            w1 += __shfl_xor_sync(0xffffffffu, w1, o);
        }
        if (lane == 0) { s_scr[40 + warp] = w0; s_scr[56 + warp] = w1; }
    }
    __syncthreads();
    if (tid < 32) {
        float v = s_scr[40 + tid];
        v += __shfl_xor_sync(0xffffffffu, v, 4, 8);
        v += __shfl_xor_sync(0xffffffffu, v, 2, 8);
        v += __shfl_xor_sync(0xffffffffu, v, 1, 8);
        if ((tid & 7) == 0) s_scr[72 + (tid >> 3)] = v;
    }
    __syncthreads();
    float rc0 = __fdividef(e0, s_scr[72 + r0]);
    float rc1 = __fdividef(e1, s_scr[74 + r0]);

    // ---- new read weights ----
    {
        int rA = r0, rB = r0 + 2;
        float rnA = s_rm[rA * 3] * s_bwd[rA * 256 + m]
                  + s_rm[rA * 3 + 1] * s_fwd[rA * 256 + m]
                  + s_rm[rA * 3 + 2] * rc0;
        float rnB = s_rm[rB * 3] * s_bwd[rB * 256 + m]
                  + s_rm[rB * 3 + 1] * s_fwd[rB * 256 + m]
                  + s_rm[rB * 3 + 2] * rc1;
        s_rwn[rA * 256 + m] = rnA;
        s_rwn[rB * 256 + m] = rnB;
        g_rw[b * 1024 + rA * 256 + m] = rnA;
        g_rw[b * 1024 + rB * 256 + m] = rnB;
    }
    __syncthreads();

    // ---- read vectors (2 threads per output element) ----
    {
        int o = tid & 255, half = tid >> 8;
        int r = o >> 6, w = o & 63;
        float acc = 0.f;
        int mstart = half * 128;
        #pragma unroll 4
        for (int mm2 = mstart; mm2 < mstart + 128; mm2++)
            acc += s_rwn[r * 256 + mm2] * s_mem[mm2 * 65 + w];
        s_red[tid] = acc;
    }
    __syncthreads();
    if (tid < 256)
        g_ys[((long)(b * TT + t)) * NNOUT + 512 + tid] = s_red[tid] + s_red[tid + 256];
}

// ---------------- host orchestration ----------------
extern "C" void kernel_launch(void* const* d_in, const int* in_sizes, int n_in,
                              void* d_out, int out_size)
{
    const float* x    = (const float*)d_in[0];
    const float* h0   = (const float*)d_in[1];
    const float* Wih0 = (const float*)d_in[2];
    const float* Whh0 = (const float*)d_in[3];
    const float* bih0 = (const float*)d_in[4];
    const float* bhh0 = (const float*)d_in[5];
    const float* Wih1 = (const float*)d_in[6];
    const float* Whh1 = (const float*)d_in[7];
    const float* bih1 = (const float*)d_in[8];
    const float* bhh1 = (const float*)d_in[9];
    const float* Wif  = (const float*)d_in[10];
    const float* bif  = (const float*)d_in[11];
    const float* Wout = (const float*)d_in[12];
    const float* bout = (const float*)d_in[13];
    float* out = (float*)d_out;
    (void)in_sizes; (void)n_in; (void)out_size;

    (void)cudaFuncSetAttribute(mem_kernel, cudaFuncAttributeMaxDynamicSharedMemorySize,
                               MEM_SMEM_FLOATS * 4);

    float *p_h0, *p_in1, *p_ys, *p_Wih0p, *p_bp0, *p_xprojp;
    cudaGetSymbolAddress((void**)&p_xprojp, g_xprojp);
    cudaGetSymbolAddress((void**)&p_h0, g_h0buf);
    cudaGetSymbolAddress((void**)&p_in1, g_in1);
    cudaGetSymbolAddress((void**)&p_ys, g_ys);
    cudaGetSymbolAddress((void**)&p_Wih0p, g_Wih0p);
    cudaGetSymbolAddress((void**)&p_bp0, g_bp0);

    init_kernel<<<16384, 256>>>(h0, Wih0, Whh0, bih0, bhh0,
                                Wih1, Whh1, bih1, bhh1, Wif);

    // xprojp: (B*T,256) @ Wih0p^T + bp0 -> [b*T+t][4h+g]
    gemm_bt<<<dim3(G4H / 32, (BB * TT) / 64, 1), 256>>>(
        x, 256, p_Wih0p, 256, p_xprojp, G4H, G4H, 256, p_bp0, 0);

    for (int t = 0; t < TT; t++) {
        int p = t & 1;
        stageA_kernel<<<256, 256>>>(t, p_h0 + p * (BB * HH),
                                    p_h0 + (p ^ 1) * (BB * HH),
                                    p_in1 + p * (BB * 1024));
        lstm1_kernel<<<128, 256>>>(t, p_in1 + p * (BB * 1024),
                                   p_in1 + (p ^ 1) * (BB * 1024));
        mem_kernel<<<BB, 512, MEM_SMEM_FLOATS * 4>>>(t, bif);
    }

    // final: out = tanh(ys) @ Wout^T + bout (tanh folded into A-load)
    gemm_bt<<<dim3(256 / 32, (BB * TT) / 64, 1), 256>>>(
        p_ys, NNOUT, Wout, NNOUT, out, 256, 256, NNOUT, bout, 1);
}